// round 1
// baseline (speedup 1.0000x reference)
#include <cuda_runtime.h>
#include <cuda_bf16.h>
#include <math_constants.h>

// ============================================================================
// CrossAttention baseline (fp32 SIMT), decomposed as:
//   1) Q = S2 @ Wq          [16384,512]x[512,1024]
//   2) K = S1 @ Wk          [16384,512]x[512,1024]
//   3) V = S1 @ Wv          [16384,512]x[512,1024]
//   4) S = Q @ K^T (batched, per b)  [2048,1024]x[1024,2048]
//   5) P = softmax_rows(S)
//   6) O = P @ V  (batched) [2048,2048]x[2048,1024]
//   7) out = O @ Wo + bo    [16384,1024]x[1024,512]
// Scratch lives in __device__ globals (no allocation anywhere).
// ============================================================================

static constexpr int B_   = 8;
static constexpr int N1_  = 2048;
static constexpr int N2_  = 2048;
static constexpr int QD   = 512;
static constexpr int ID   = 1024;   // inner dim
static constexpr long long QKV_ELEMS = (long long)B_ * N2_ * ID;      // 16,777,216
static constexpr long long SC_ELEMS  = (long long)B_ * N2_ * N1_;     // 33,554,432

__device__ float g_Q[QKV_ELEMS];
__device__ float g_K[QKV_ELEMS];
__device__ float g_V[QKV_ELEMS];
__device__ float g_S[SC_ELEMS];
__device__ float g_O[QKV_ELEMS];

// ---------------------------------------------------------------------------
// Generic tiled SIMT GEMM: C[M,N] = A[M,K] * B (NN or NT) (+ bias)
// BM=BN=128, BK=8, 256 threads, 8x8 per-thread microtile.
// All problem dims here are multiples of the tile sizes -> no bounds checks.
// ---------------------------------------------------------------------------
#define BM 128
#define BN 128
#define BK 8
#define TM 8
#define TN 8

template <bool BT, bool BIAS>
__global__ __launch_bounds__(256)
void gemm_kernel(const float* __restrict__ A, const float* __restrict__ Bm,
                 const float* __restrict__ bias, float* __restrict__ C,
                 int M, int N, int K,
                 long long strideA, long long strideB, long long strideC)
{
    __shared__ float As[BK][BM];
    __shared__ float Bs[BK][BN];

    const int bz = blockIdx.z;
    A  += (long long)bz * strideA;
    Bm += (long long)bz * strideB;
    C  += (long long)bz * strideC;

    const int bm = blockIdx.y * BM;
    const int bn = blockIdx.x * BN;
    const int tid = threadIdx.x;
    const int ty = tid >> 4;        // 0..15
    const int tx = tid & 15;        // 0..15

    float acc[TM][TN];
#pragma unroll
    for (int i = 0; i < TM; i++)
#pragma unroll
        for (int j = 0; j < TN; j++) acc[i][j] = 0.0f;

    // A loader: 128 rows x 8 k-cols, float4 along k per thread
    const int a_row = tid >> 1;             // 0..127
    const int a_k4  = (tid & 1) * 4;        // 0 or 4
    // B loader (NN): 8 k-rows x 128 n-cols
    const int b_k  = tid >> 5;              // 0..7
    const int b_n4 = (tid & 31) * 4;        // 0..124
    // B loader (NT): B is [N,K] row-major; read float4 along k
    const int bt_n  = tid >> 1;             // 0..127
    const int bt_k4 = (tid & 1) * 4;        // 0 or 4

    for (int k0 = 0; k0 < K; k0 += BK) {
        // ---- load A tile (transposed into As[k][m]) ----
        float4 av = *reinterpret_cast<const float4*>(
            A + (long long)(bm + a_row) * K + (k0 + a_k4));
        As[a_k4 + 0][a_row] = av.x;
        As[a_k4 + 1][a_row] = av.y;
        As[a_k4 + 2][a_row] = av.z;
        As[a_k4 + 3][a_row] = av.w;

        // ---- load B tile into Bs[k][n] ----
        if (!BT) {
            float4 bv = *reinterpret_cast<const float4*>(
                Bm + (long long)(k0 + b_k) * N + (bn + b_n4));
            *reinterpret_cast<float4*>(&Bs[b_k][b_n4]) = bv;
        } else {
            float4 bv = *reinterpret_cast<const float4*>(
                Bm + (long long)(bn + bt_n) * K + (k0 + bt_k4));
            Bs[bt_k4 + 0][bt_n] = bv.x;
            Bs[bt_k4 + 1][bt_n] = bv.y;
            Bs[bt_k4 + 2][bt_n] = bv.z;
            Bs[bt_k4 + 3][bt_n] = bv.w;
        }
        __syncthreads();

#pragma unroll
        for (int kk = 0; kk < BK; kk++) {
            float ra[TM], rb[TN];
            *reinterpret_cast<float4*>(&ra[0]) =
                *reinterpret_cast<const float4*>(&As[kk][ty * TM]);
            *reinterpret_cast<float4*>(&ra[4]) =
                *reinterpret_cast<const float4*>(&As[kk][ty * TM + 4]);
            *reinterpret_cast<float4*>(&rb[0]) =
                *reinterpret_cast<const float4*>(&Bs[kk][tx * TN]);
            *reinterpret_cast<float4*>(&rb[4]) =
                *reinterpret_cast<const float4*>(&Bs[kk][tx * TN + 4]);
#pragma unroll
            for (int i = 0; i < TM; i++)
#pragma unroll
                for (int j = 0; j < TN; j++)
                    acc[i][j] = fmaf(ra[i], rb[j], acc[i][j]);
        }
        __syncthreads();
    }

    // ---- epilogue ----
#pragma unroll
    for (int i = 0; i < TM; i++) {
        const long long row = bm + ty * TM + i;
#pragma unroll
        for (int j = 0; j < TN; j += 4) {
            const int col = bn + tx * TN + j;
            float4 v = make_float4(acc[i][j], acc[i][j + 1], acc[i][j + 2], acc[i][j + 3]);
            if (BIAS) {
                v.x += bias[col];
                v.y += bias[col + 1];
                v.z += bias[col + 2];
                v.w += bias[col + 3];
            }
            *reinterpret_cast<float4*>(C + row * N + col) = v;
        }
    }
}

// ---------------------------------------------------------------------------
// Row softmax over N=2048 (one block of 256 threads per row, regs-resident)
// ---------------------------------------------------------------------------
__global__ __launch_bounds__(256)
void softmax_kernel(float* __restrict__ S)
{
    const int N = 2048;
    const long long row = blockIdx.x;
    float* p = S + row * N;
    const int t = threadIdx.x;

    float v[8];
#pragma unroll
    for (int u = 0; u < 8; u++) v[u] = p[t + u * 256];

    float mx = v[0];
#pragma unroll
    for (int u = 1; u < 8; u++) mx = fmaxf(mx, v[u]);

    __shared__ float red[256];
    red[t] = mx;
    __syncthreads();
    for (int s = 128; s > 0; s >>= 1) {
        if (t < s) red[t] = fmaxf(red[t], red[t + s]);
        __syncthreads();
    }
    mx = red[0];
    __syncthreads();

    float sum = 0.0f;
#pragma unroll
    for (int u = 0; u < 8; u++) {
        v[u] = __expf(v[u] - mx);
        sum += v[u];
    }
    red[t] = sum;
    __syncthreads();
    for (int s = 128; s > 0; s >>= 1) {
        if (t < s) red[t] += red[t + s];
        __syncthreads();
    }
    const float inv = __frcp_rn(red[0]);

#pragma unroll
    for (int u = 0; u < 8; u++) p[t + u * 256] = v[u] * inv;
}

// ---------------------------------------------------------------------------
// kernel_launch — graph-capturable, allocation-free.
// Input order (metadata): S1, S2, Wq, Wk, Wv, Wo, bo. Output: fp32 [8,2048,512].
// ---------------------------------------------------------------------------
extern "C" void kernel_launch(void* const* d_in, const int* in_sizes, int n_in,
                              void* d_out, int out_size)
{
    const float* S1 = (const float*)d_in[0];
    const float* S2 = (const float*)d_in[1];
    const float* Wq = (const float*)d_in[2];
    const float* Wk = (const float*)d_in[3];
    const float* Wv = (const float*)d_in[4];
    const float* Wo = (const float*)d_in[5];
    const float* bo = (const float*)d_in[6];
    float* out = (float*)d_out;

    float *Q, *Km, *Vm, *Sc, *O;
    cudaGetSymbolAddress((void**)&Q,  g_Q);
    cudaGetSymbolAddress((void**)&Km, g_K);
    cudaGetSymbolAddress((void**)&Vm, g_V);
    cudaGetSymbolAddress((void**)&Sc, g_S);
    cudaGetSymbolAddress((void**)&O,  g_O);

    const int MQ = B_ * N2_;   // 16384 rows for the flattened projections

    // 1-3) projections
    gemm_kernel<false, false><<<dim3(ID / BN, MQ / BM, 1), 256>>>(
        S2, Wq, nullptr, Q, MQ, ID, QD, 0, 0, 0);
    gemm_kernel<false, false><<<dim3(ID / BN, MQ / BM, 1), 256>>>(
        S1, Wk, nullptr, Km, MQ, ID, QD, 0, 0, 0);
    gemm_kernel<false, false><<<dim3(ID / BN, MQ / BM, 1), 256>>>(
        S1, Wv, nullptr, Vm, MQ, ID, QD, 0, 0, 0);

    // 4) scores = Q @ K^T (batched over B_)
    gemm_kernel<true, false><<<dim3(N1_ / BN, N2_ / BM, B_), 256>>>(
        Q, Km, nullptr, Sc, N2_, N1_, ID,
        (long long)N2_ * ID, (long long)N1_ * ID, (long long)N2_ * N1_);

    // 5) softmax over rows
    softmax_kernel<<<B_ * N2_, 256>>>(Sc);

    // 6) O = P @ V (batched)
    gemm_kernel<false, false><<<dim3(ID / BN, N2_ / BM, B_), 256>>>(
        Sc, Vm, nullptr, O, N2_, ID, N1_,
        (long long)N2_ * N1_, (long long)N1_ * ID, (long long)N2_ * ID);

    // 7) out = O @ Wo + bo
    gemm_kernel<false, true><<<dim3(QD / BN, MQ / BM, 1), 256>>>(
        O, Wo, bo, out, MQ, QD, ID, 0, 0, 0);
}

// round 4
// speedup vs baseline: 2.1277x; 2.1277x over previous
#include <cuda_runtime.h>
#include <cuda_bf16.h>
#include <cstdint>

using bf16 = __nv_bfloat16;
using ll = long long;

// ============================================================================
// CrossAttention via mma.sync (HMMA) bf16 split (hi+lo), fp32-class accuracy.
// (tcgen05 is rejected by this harness's compute_103 PTX target; mma.sync,
//  ldmatrix and cp.async are baseline features and hit the tensor pipe.)
//   G1: Q  = S2·WqT^T        -> split bf16
//   G2: K  = S1·WkT^T        -> split bf16
//   G3: VT = WvT·S1^T (NT)   -> split bf16   (V produced pre-transposed)
//   G4: S  = Q·K^T           -> fp32
//   SM: P  = softmax(S)      -> split bf16
//   G6: O  = P·VT^T          -> split bf16
//   G7: out= O·WoT^T + bo    -> fp32
// All GEMMs NT: C[m,n] = sum_k A[m,k]*B[n,k], A/B given as (hi,lo) bf16.
// ============================================================================

static constexpr int B_  = 8;
static constexpr int N1_ = 2048;
static constexpr int N2_ = 2048;
static constexpr int QD  = 512;
static constexpr int ID  = 1024;

static constexpr ll S_ELEMS  = (ll)B_ * N2_ * QD;
static constexpr ll QK_ELEMS = (ll)B_ * N2_ * ID;
static constexpr ll SC_ELEMS = (ll)B_ * N2_ * N1_;

__device__ bf16 g_s1h[S_ELEMS], g_s1l[S_ELEMS];
__device__ bf16 g_s2h[S_ELEMS], g_s2l[S_ELEMS];
__device__ bf16 g_wqth[ID * QD], g_wqtl[ID * QD];
__device__ bf16 g_wkth[ID * QD], g_wktl[ID * QD];
__device__ bf16 g_wvth[ID * QD], g_wvtl[ID * QD];
__device__ bf16 g_woth[QD * ID], g_wotl[QD * ID];
__device__ bf16 g_qh[QK_ELEMS], g_ql[QK_ELEMS];
__device__ bf16 g_kh[QK_ELEMS], g_kl[QK_ELEMS];
__device__ bf16 g_vth[QK_ELEMS], g_vtl[QK_ELEMS];
__device__ float g_sc[SC_ELEMS];
__device__ bf16 g_ph[SC_ELEMS], g_pl[SC_ELEMS];
__device__ bf16 g_oh[QK_ELEMS], g_ol[QK_ELEMS];

// ---------------------------------------------------------------------------
// PTX helpers (baseline sm_80-class instructions only)
// ---------------------------------------------------------------------------
__device__ __forceinline__ uint32_t smem_u32(const void* p) {
    uint32_t a;
    asm("{ .reg .u64 t; cvta.to.shared.u64 t, %1; cvt.u32.u64 %0, t; }"
        : "=r"(a) : "l"(p));
    return a;
}
__device__ __forceinline__ void cp16(uint32_t s, const void* g) {
    asm volatile("cp.async.cg.shared.global [%0], [%1], 16;"
                 :: "r"(s), "l"(g) : "memory");
}
__device__ __forceinline__ void cp_commit() {
    asm volatile("cp.async.commit_group;" ::: "memory");
}
template <int N>
__device__ __forceinline__ void cp_wait() {
    asm volatile("cp.async.wait_group %0;" :: "n"(N) : "memory");
}
__device__ __forceinline__ void ldsm4(uint32_t* r, uint32_t addr) {
    asm volatile("ldmatrix.sync.aligned.m8n8.x4.shared.b16 {%0,%1,%2,%3}, [%4];"
                 : "=r"(r[0]), "=r"(r[1]), "=r"(r[2]), "=r"(r[3]) : "r"(addr));
}
__device__ __forceinline__ void mma_bf16(float* c, const uint32_t* a,
                                         uint32_t b0, uint32_t b1) {
    asm volatile(
        "mma.sync.aligned.m16n8k16.row.col.f32.bf16.bf16.f32 "
        "{%0,%1,%2,%3}, {%4,%5,%6,%7}, {%8,%9}, {%0,%1,%2,%3};"
        : "+f"(c[0]), "+f"(c[1]), "+f"(c[2]), "+f"(c[3])
        : "r"(a[0]), "r"(a[1]), "r"(a[2]), "r"(a[3]), "r"(b0), "r"(b1));
}

// ---------------------------------------------------------------------------
// GEMM: BM=BN=128, BK=32, 256 thr, warp grid 2(M)x4(N), 3-stage cp.async.
// smem rows padded to 80 B (40 bf16) -> ldmatrix conflict-free.
// EPI: 0 = fp32 out, 1 = fp32 + bias, 2 = split bf16 (hi, lo) out.
// ---------------------------------------------------------------------------
static constexpr int BM = 128, BN = 128, BK = 32;
static constexpr int ROWB = 80;                  // padded row bytes (40 bf16)
static constexpr int A_H = 0;
static constexpr int A_L = 10240;                // 128*80
static constexpr int B_H = 20480;
static constexpr int B_L = 30720;
static constexpr int STAGE = 40960;
static constexpr int NSTAGE = 3;
static constexpr int SMEM_SZ = NSTAGE * STAGE;   // 122880

template <int EPI>
__global__ __launch_bounds__(256, 1)
void mma_gemm(const bf16* __restrict__ Ah, const bf16* __restrict__ Al,
              const bf16* __restrict__ Bh, const bf16* __restrict__ Bl,
              float* __restrict__ Cf, bf16* __restrict__ Ch, bf16* __restrict__ Cl,
              const float* __restrict__ bias,
              int M, int N, int K, ll sA, ll sB, ll sC)
{
    extern __shared__ char smem[];
    const uint32_t sb = smem_u32(smem);
    const int tid = threadIdx.x;
    const int bz  = blockIdx.z;
    const int bm  = blockIdx.y * BM;
    const int bn  = blockIdx.x * BN;

    const bf16* pAh = Ah + (ll)bz * sA;
    const bf16* pAl = Al + (ll)bz * sA;
    const bf16* pBh = Bh + (ll)bz * sB;
    const bf16* pBl = Bl + (ll)bz * sB;

    // per-stage loader: 512 16B-chunks per matrix (128 rows x 4), 8 cp/thread
    auto load_stage = [&](int buf, int k0) {
        const uint32_t s = sb + buf * STAGE;
#pragma unroll
        for (int it = 0; it < 2; it++) {
            const int g = tid + it * 256;
            const int r = g >> 2, c = g & 3;
            const uint32_t so = r * ROWB + c * 16;
            const ll ga = (ll)(bm + r) * K + k0 + c * 8;
            const ll gb = (ll)(bn + r) * K + k0 + c * 8;
            cp16(s + A_H + so, pAh + ga);
            cp16(s + A_L + so, pAl + ga);
            cp16(s + B_H + so, pBh + gb);
            cp16(s + B_L + so, pBl + gb);
        }
    };

    const int nk = K / BK;
    load_stage(0, 0);      cp_commit();
    load_stage(1, BK);     cp_commit();
    load_stage(2, 2 * BK); cp_commit();

    const int lane = tid & 31, wid = tid >> 5;
    const int wm = (wid & 1) * 64;          // 2 warps along M
    const int wn = (wid >> 1) * 32;         // 4 warps along N
    const int lr = lane & 15;               // ldmatrix row-in-16
    const int lk = (lane >> 4) * 16;        // 16B k-offset

    float acc[4][4][4];
#pragma unroll
    for (int mt = 0; mt < 4; mt++)
#pragma unroll
        for (int nt = 0; nt < 4; nt++)
#pragma unroll
            for (int j = 0; j < 4; j++) acc[mt][nt][j] = 0.0f;

    for (int i = 0; i < nk; i++) {
        cp_wait<NSTAGE - 1>();
        __syncthreads();
        const uint32_t s = sb + (i % NSTAGE) * STAGE;

#pragma unroll
        for (int ks = 0; ks < 2; ks++) {    // two k16 steps per BK=32
            uint32_t ah[4][4], al[4][4], bh[2][4], bl[2][4];
#pragma unroll
            for (int mt = 0; mt < 4; mt++) {
                const uint32_t ad = s + A_H + (wm + mt * 16 + lr) * ROWB + ks * 32 + lk;
                ldsm4(ah[mt], ad);
                ldsm4(al[mt], ad + (A_L - A_H));
            }
#pragma unroll
            for (int p = 0; p < 2; p++) {
                const uint32_t bd = s + B_H + (wn + p * 16 + lr) * ROWB + ks * 32 + lk;
                ldsm4(bh[p], bd);
                ldsm4(bl[p], bd + (B_L - B_H));
            }
            // pass 0: Ah*Bh
#pragma unroll
            for (int mt = 0; mt < 4; mt++)
#pragma unroll
                for (int nt = 0; nt < 4; nt++)
                    mma_bf16(acc[mt][nt], ah[mt],
                             bh[nt >> 1][nt & 1], bh[nt >> 1][2 + (nt & 1)]);
            // pass 1: Ah*Bl
#pragma unroll
            for (int mt = 0; mt < 4; mt++)
#pragma unroll
                for (int nt = 0; nt < 4; nt++)
                    mma_bf16(acc[mt][nt], ah[mt],
                             bl[nt >> 1][nt & 1], bl[nt >> 1][2 + (nt & 1)]);
            // pass 2: Al*Bh
#pragma unroll
            for (int mt = 0; mt < 4; mt++)
#pragma unroll
                for (int nt = 0; nt < 4; nt++)
                    mma_bf16(acc[mt][nt], al[mt],
                             bh[nt >> 1][nt & 1], bh[nt >> 1][2 + (nt & 1)]);
        }

        __syncthreads();
        if (i + NSTAGE < nk) load_stage(i % NSTAGE, (i + NSTAGE) * BK);
        cp_commit();
    }

    // ---- epilogue ----
    const int er = lane >> 2;
    const int ec = (lane & 3) * 2;
#pragma unroll
    for (int mt = 0; mt < 4; mt++) {
#pragma unroll
        for (int nt = 0; nt < 4; nt++) {
            const int row = bm + wm + mt * 16 + er;
            const int col = bn + wn + nt * 8 + ec;
            const ll o0 = (ll)bz * sC + (ll)row * N + col;
            const ll o8 = o0 + 8LL * N;
            float c0 = acc[mt][nt][0], c1 = acc[mt][nt][1];
            float c2 = acc[mt][nt][2], c3 = acc[mt][nt][3];
            if (EPI == 2) {
                bf16 h0 = __float2bfloat16(c0), h1 = __float2bfloat16(c1);
                bf16 h2 = __float2bfloat16(c2), h3 = __float2bfloat16(c3);
                *(__nv_bfloat162*)(Ch + o0) = __halves2bfloat162(h0, h1);
                *(__nv_bfloat162*)(Ch + o8) = __halves2bfloat162(h2, h3);
                *(__nv_bfloat162*)(Cl + o0) = __halves2bfloat162(
                    __float2bfloat16(c0 - __bfloat162float(h0)),
                    __float2bfloat16(c1 - __bfloat162float(h1)));
                *(__nv_bfloat162*)(Cl + o8) = __halves2bfloat162(
                    __float2bfloat16(c2 - __bfloat162float(h2)),
                    __float2bfloat16(c3 - __bfloat162float(h3)));
            } else {
                if (EPI == 1) {
                    const float b0 = bias[col], b1 = bias[col + 1];
                    c0 += b0; c1 += b1; c2 += b0; c3 += b1;
                }
                *(float2*)(Cf + o0) = make_float2(c0, c1);
                *(float2*)(Cf + o8) = make_float2(c2, c3);
            }
        }
    }
}

// ---------------------------------------------------------------------------
// fp32 -> (hi, lo) bf16 split, elementwise
// ---------------------------------------------------------------------------
__global__ __launch_bounds__(256)
void split_kernel(const float* __restrict__ in, bf16* __restrict__ h,
                  bf16* __restrict__ l, ll n4)
{
    ll i = (ll)blockIdx.x * 256 + threadIdx.x;
    if (i >= n4) return;
    float4 v = *(const float4*)(in + i * 4);
    float f[4] = {v.x, v.y, v.z, v.w};
    bf16 hh[4], lo[4];
#pragma unroll
    for (int j = 0; j < 4; j++) {
        hh[j] = __float2bfloat16(f[j]);
        lo[j] = __float2bfloat16(f[j] - __bfloat162float(hh[j]));
    }
    *(__nv_bfloat162*)(h + i * 4)     = __halves2bfloat162(hh[0], hh[1]);
    *(__nv_bfloat162*)(h + i * 4 + 2) = __halves2bfloat162(hh[2], hh[3]);
    *(__nv_bfloat162*)(l + i * 4)     = __halves2bfloat162(lo[0], lo[1]);
    *(__nv_bfloat162*)(l + i * 4 + 2) = __halves2bfloat162(lo[2], lo[3]);
}

// ---------------------------------------------------------------------------
// Transpose + split: W[R,C] fp32 -> T[C,R] (hi, lo) bf16
// ---------------------------------------------------------------------------
__global__ __launch_bounds__(256)
void tsplit_kernel(const float* __restrict__ W, bf16* __restrict__ Th,
                   bf16* __restrict__ Tl, int R, int C)
{
    __shared__ float t[32][33];
    const int bx = blockIdx.x * 32;   // C index
    const int by = blockIdx.y * 32;   // R index
    const int x = threadIdx.x, y = threadIdx.y;   // (32, 8)
#pragma unroll
    for (int j = 0; j < 32; j += 8)
        t[y + j][x] = W[(ll)(by + y + j) * C + bx + x];
    __syncthreads();
#pragma unroll
    for (int j = 0; j < 32; j += 8) {
        float f = t[x][y + j];
        bf16 h = __float2bfloat16(f);
        bf16 l = __float2bfloat16(f - __bfloat162float(h));
        Th[(ll)(bx + y + j) * R + by + x] = h;
        Tl[(ll)(bx + y + j) * R + by + x] = l;
    }
}

// ---------------------------------------------------------------------------
// Row softmax over N=2048, emits split bf16 probabilities
// ---------------------------------------------------------------------------
__global__ __launch_bounds__(256)
void softmax_split_kernel(const float* __restrict__ S, bf16* __restrict__ Ph,
                          bf16* __restrict__ Pl)
{
    const int N = 2048;
    const ll row = blockIdx.x;
    const float* p = S + row * N;
    const int t = threadIdx.x;

    float v[8];
#pragma unroll
    for (int u = 0; u < 8; u++) v[u] = p[t + u * 256];

    float mx = v[0];
#pragma unroll
    for (int u = 1; u < 8; u++) mx = fmaxf(mx, v[u]);

    __shared__ float red[256];
    red[t] = mx;
    __syncthreads();
    for (int s = 128; s > 0; s >>= 1) {
        if (t < s) red[t] = fmaxf(red[t], red[t + s]);
        __syncthreads();
    }
    mx = red[0];
    __syncthreads();

    float sum = 0.0f;
#pragma unroll
    for (int u = 0; u < 8; u++) {
        v[u] = __expf(v[u] - mx);
        sum += v[u];
    }
    red[t] = sum;
    __syncthreads();
    for (int s = 128; s > 0; s >>= 1) {
        if (t < s) red[t] += red[t + s];
        __syncthreads();
    }
    const float inv = __frcp_rn(red[0]);

#pragma unroll
    for (int u = 0; u < 8; u++) {
        float pr = v[u] * inv;
        bf16 h = __float2bfloat16(pr);
        bf16 l = __float2bfloat16(pr - __bfloat162float(h));
        Ph[row * N + t + u * 256] = h;
        Pl[row * N + t + u * 256] = l;
    }
}

// ---------------------------------------------------------------------------
// kernel_launch — graph-capturable, allocation-free
// Inputs: S1, S2, Wq, Wk, Wv, Wo, bo. Output: fp32 [8,2048,512].
// ---------------------------------------------------------------------------
extern "C" void kernel_launch(void* const* d_in, const int* in_sizes, int n_in,
                              void* d_out, int out_size)
{
    const float* S1 = (const float*)d_in[0];
    const float* S2 = (const float*)d_in[1];
    const float* Wq = (const float*)d_in[2];
    const float* Wk = (const float*)d_in[3];
    const float* Wv = (const float*)d_in[4];
    const float* Wo = (const float*)d_in[5];
    const float* bo = (const float*)d_in[6];
    float* out = (float*)d_out;

    bf16 *s1h, *s1l, *s2h, *s2l, *wqth, *wqtl, *wkth, *wktl, *wvth, *wvtl,
         *woth, *wotl, *qh, *ql, *kh, *kl, *vth, *vtl, *ph, *pl, *oh, *ol;
    float* sc;
    cudaGetSymbolAddress((void**)&s1h, g_s1h);  cudaGetSymbolAddress((void**)&s1l, g_s1l);
    cudaGetSymbolAddress((void**)&s2h, g_s2h);  cudaGetSymbolAddress((void**)&s2l, g_s2l);
    cudaGetSymbolAddress((void**)&wqth, g_wqth); cudaGetSymbolAddress((void**)&wqtl, g_wqtl);
    cudaGetSymbolAddress((void**)&wkth, g_wkth); cudaGetSymbolAddress((void**)&wktl, g_wktl);
    cudaGetSymbolAddress((void**)&wvth, g_wvth); cudaGetSymbolAddress((void**)&wvtl, g_wvtl);
    cudaGetSymbolAddress((void**)&woth, g_woth); cudaGetSymbolAddress((void**)&wotl, g_wotl);
    cudaGetSymbolAddress((void**)&qh, g_qh);    cudaGetSymbolAddress((void**)&ql, g_ql);
    cudaGetSymbolAddress((void**)&kh, g_kh);    cudaGetSymbolAddress((void**)&kl, g_kl);
    cudaGetSymbolAddress((void**)&vth, g_vth);  cudaGetSymbolAddress((void**)&vtl, g_vtl);
    cudaGetSymbolAddress((void**)&sc, g_sc);
    cudaGetSymbolAddress((void**)&ph, g_ph);    cudaGetSymbolAddress((void**)&pl, g_pl);
    cudaGetSymbolAddress((void**)&oh, g_oh);    cudaGetSymbolAddress((void**)&ol, g_ol);

    cudaFuncSetAttribute(mma_gemm<0>, cudaFuncAttributeMaxDynamicSharedMemorySize, SMEM_SZ);
    cudaFuncSetAttribute(mma_gemm<1>, cudaFuncAttributeMaxDynamicSharedMemorySize, SMEM_SZ);
    cudaFuncSetAttribute(mma_gemm<2>, cudaFuncAttributeMaxDynamicSharedMemorySize, SMEM_SZ);

    const int MQ = B_ * N2_;   // 16384

    // ---- pre-pass: split activations, transpose+split weights ----
    split_kernel<<<(unsigned)(S_ELEMS / 4 / 256), 256>>>(S1, s1h, s1l, S_ELEMS / 4);
    split_kernel<<<(unsigned)(S_ELEMS / 4 / 256), 256>>>(S2, s2h, s2l, S_ELEMS / 4);
    tsplit_kernel<<<dim3(ID / 32, QD / 32), dim3(32, 8)>>>(Wq, wqth, wqtl, QD, ID);
    tsplit_kernel<<<dim3(ID / 32, QD / 32), dim3(32, 8)>>>(Wk, wkth, wktl, QD, ID);
    tsplit_kernel<<<dim3(ID / 32, QD / 32), dim3(32, 8)>>>(Wv, wvth, wvtl, QD, ID);
    tsplit_kernel<<<dim3(QD / 32, ID / 32), dim3(32, 8)>>>(Wo, woth, wotl, ID, QD);

    // ---- G1: Q = S2 · WqT^T  [16384,1024], K=512 ----
    mma_gemm<2><<<dim3(ID / BN, MQ / BM, 1), 256, SMEM_SZ>>>(
        s2h, s2l, wqth, wqtl, nullptr, qh, ql, nullptr, MQ, ID, QD, 0, 0, 0);
    // ---- G2: K = S1 · WkT^T ----
    mma_gemm<2><<<dim3(ID / BN, MQ / BM, 1), 256, SMEM_SZ>>>(
        s1h, s1l, wkth, wktl, nullptr, kh, kl, nullptr, MQ, ID, QD, 0, 0, 0);
    // ---- G3: VT[b] = WvT · S1[b]^T  [1024,2048], K=512, batched ----
    mma_gemm<2><<<dim3(N1_ / BN, ID / BM, B_), 256, SMEM_SZ>>>(
        wvth, wvtl, s1h, s1l, nullptr, vth, vtl, nullptr,
        ID, N1_, QD, 0, (ll)N1_ * QD, (ll)ID * N1_);
    // ---- G4: S[b] = Q[b] · K[b]^T  [2048,2048], K=1024 ----
    mma_gemm<0><<<dim3(N1_ / BN, N2_ / BM, B_), 256, SMEM_SZ>>>(
        qh, ql, kh, kl, sc, nullptr, nullptr, nullptr,
        N2_, N1_, ID, (ll)N2_ * ID, (ll)N1_ * ID, (ll)N2_ * N1_);
    // ---- softmax -> split P ----
    softmax_split_kernel<<<B_ * N2_, 256>>>(sc, ph, pl);
    // ---- G6: O[b] = P[b] · VT[b]^T  [2048,1024], K=2048 ----
    mma_gemm<2><<<dim3(ID / BN, N2_ / BM, B_), 256, SMEM_SZ>>>(
        ph, pl, vth, vtl, nullptr, oh, ol, nullptr,
        N2_, ID, N1_, (ll)N2_ * N1_, (ll)ID * N1_, (ll)N2_ * ID);
    // ---- G7: out = O · WoT^T + bo  [16384,512], K=1024 ----
    mma_gemm<1><<<dim3(QD / BN, MQ / BM, 1), 256, SMEM_SZ>>>(
        oh, ol, woth, wotl, out, nullptr, nullptr, bo, MQ, QD, ID, 0, 0, 0);
}

// round 6
// speedup vs baseline: 2.1640x; 1.0171x over previous
#include <cuda_runtime.h>
#include <cuda_bf16.h>
#include <cstdint>

using bf16 = __nv_bfloat16;
using ll = long long;

// ============================================================================
// CrossAttention via mma.sync (HMMA) bf16 split (hi+lo), fp32-class accuracy.
//   G1: Q  = S2·WqT^T        -> split bf16
//   G2: K  = S1·WkT^T        -> split bf16
//   G3: VT = WvT·S1^T (NT)   -> split bf16   (V produced pre-transposed)
//   G4: S  = Q·K^T           -> fp32
//   SM: P  = softmax(S)      -> split bf16
//   G6: O  = P·VT^T          -> split bf16
//   G7: out= O·WoT^T + bo    -> fp32
// All GEMMs NT: C[m,n] = sum_k A[m,k]*B[n,k], A/B given as (hi,lo) bf16.
// R5: 128x256 block tile, 64x64 warp tile (2Mx4N warps) -> smem-traffic/MMA
//     ratio below 1.0; tensor-issue-bound instead of crossbar-bound.
// ============================================================================

static constexpr int B_  = 8;
static constexpr int N1_ = 2048;
static constexpr int N2_ = 2048;
static constexpr int QD  = 512;
static constexpr int ID  = 1024;

static constexpr ll S_ELEMS  = (ll)B_ * N2_ * QD;
static constexpr ll QK_ELEMS = (ll)B_ * N2_ * ID;
static constexpr ll SC_ELEMS = (ll)B_ * N2_ * N1_;

__device__ bf16 g_s1h[S_ELEMS], g_s1l[S_ELEMS];
__device__ bf16 g_s2h[S_ELEMS], g_s2l[S_ELEMS];
__device__ bf16 g_wqth[ID * QD], g_wqtl[ID * QD];
__device__ bf16 g_wkth[ID * QD], g_wktl[ID * QD];
__device__ bf16 g_wvth[ID * QD], g_wvtl[ID * QD];
__device__ bf16 g_woth[QD * ID], g_wotl[QD * ID];
__device__ bf16 g_qh[QK_ELEMS], g_ql[QK_ELEMS];
__device__ bf16 g_kh[QK_ELEMS], g_kl[QK_ELEMS];
__device__ bf16 g_vth[QK_ELEMS], g_vtl[QK_ELEMS];
__device__ float g_sc[SC_ELEMS];
__device__ bf16 g_ph[SC_ELEMS], g_pl[SC_ELEMS];
__device__ bf16 g_oh[QK_ELEMS], g_ol[QK_ELEMS];

// ---------------------------------------------------------------------------
// PTX helpers (baseline sm_80-class instructions only)
// ---------------------------------------------------------------------------
__device__ __forceinline__ uint32_t smem_u32(const void* p) {
    uint32_t a;
    asm("{ .reg .u64 t; cvta.to.shared.u64 t, %1; cvt.u32.u64 %0, t; }"
        : "=r"(a) : "l"(p));
    return a;
}
__device__ __forceinline__ void cp16(uint32_t s, const void* g) {
    asm volatile("cp.async.cg.shared.global [%0], [%1], 16;"
                 :: "r"(s), "l"(g) : "memory");
}
__device__ __forceinline__ void cp_commit() {
    asm volatile("cp.async.commit_group;" ::: "memory");
}
template <int N>
__device__ __forceinline__ void cp_wait() {
    asm volatile("cp.async.wait_group %0;" :: "n"(N) : "memory");
}
__device__ __forceinline__ void ldsm4(uint32_t* r, uint32_t addr) {
    asm volatile("ldmatrix.sync.aligned.m8n8.x4.shared.b16 {%0,%1,%2,%3}, [%4];"
                 : "=r"(r[0]), "=r"(r[1]), "=r"(r[2]), "=r"(r[3]) : "r"(addr));
}
__device__ __forceinline__ void mma_bf16(float* c, const uint32_t* a,
                                         uint32_t b0, uint32_t b1) {
    asm volatile(
        "mma.sync.aligned.m16n8k16.row.col.f32.bf16.bf16.f32 "
        "{%0,%1,%2,%3}, {%4,%5,%6,%7}, {%8,%9}, {%0,%1,%2,%3};"
        : "+f"(c[0]), "+f"(c[1]), "+f"(c[2]), "+f"(c[3])
        : "r"(a[0]), "r"(a[1]), "r"(a[2]), "r"(a[3]), "r"(b0), "r"(b1));
}

// ---------------------------------------------------------------------------
// GEMM: BM=128, BN=256, BK=32, 256 thr, warp grid 2(M)x4(N) -> 64x64/warp.
// smem rows padded to 80 B -> ldmatrix conflict-free. 3-stage cp.async.
// EPI: 0 = fp32 out, 1 = fp32 + bias, 2 = split bf16 (hi, lo) out.
// ---------------------------------------------------------------------------
static constexpr int BM = 128, BN = 256, BK = 32;
static constexpr int ROWB = 80;                  // padded row bytes (40 bf16)
static constexpr int A_H = 0;
static constexpr int A_L = 10240;                // 128*80
static constexpr int B_H = 20480;
static constexpr int B_L = 40960;                // B_H + 256*80
static constexpr int STAGE = 61440;
static constexpr int NSTAGE = 3;
static constexpr int SMEM_SZ = NSTAGE * STAGE;   // 184320

template <int EPI>
__global__ __launch_bounds__(256, 1)
void mma_gemm(const bf16* __restrict__ Ah, const bf16* __restrict__ Al,
              const bf16* __restrict__ Bh, const bf16* __restrict__ Bl,
              float* __restrict__ Cf, bf16* __restrict__ Ch, bf16* __restrict__ Cl,
              const float* __restrict__ bias,
              int M, int N, int K, ll sA, ll sB, ll sC)
{
    extern __shared__ char smem[];
    const uint32_t sb = smem_u32(smem);
    const int tid = threadIdx.x;
    const int bz  = blockIdx.z;
    const int bm  = blockIdx.y * BM;
    const int bn  = blockIdx.x * BN;

    const bf16* pAh = Ah + (ll)bz * sA;
    const bf16* pAl = Al + (ll)bz * sA;
    const bf16* pBh = Bh + (ll)bz * sB;
    const bf16* pBl = Bl + (ll)bz * sB;

    // per-stage loader: A 512 chunks x2, B 1024 chunks x2 (16B each)
    auto load_stage = [&](int buf, int k0) {
        const uint32_t s = sb + buf * STAGE;
#pragma unroll
        for (int it = 0; it < 2; it++) {
            const int g = tid + it * 256;          // 0..511
            const int r = g >> 2, c = g & 3;
            const uint32_t so = r * ROWB + c * 16;
            const ll ga = (ll)(bm + r) * K + k0 + c * 8;
            cp16(s + A_H + so, pAh + ga);
            cp16(s + A_L + so, pAl + ga);
        }
#pragma unroll
        for (int it = 0; it < 4; it++) {
            const int g = tid + it * 256;          // 0..1023
            const int r = g >> 2, c = g & 3;
            const uint32_t so = r * ROWB + c * 16;
            const ll gb = (ll)(bn + r) * K + k0 + c * 8;
            cp16(s + B_H + so, pBh + gb);
            cp16(s + B_L + so, pBl + gb);
        }
    };

    const int nk = K / BK;
    load_stage(0, 0);      cp_commit();
    load_stage(1, BK);     cp_commit();
    load_stage(2, 2 * BK); cp_commit();

    const int lane = tid & 31, wid = tid >> 5;
    const int wm = (wid & 1) * 64;          // 2 warps along M
    const int wn = (wid >> 1) * 64;         // 4 warps along N
    const int lr = lane & 15;               // ldmatrix row-in-16
    const int lk = (lane >> 4) * 16;        // 16B k-offset

    float acc[4][8][4];
#pragma unroll
    for (int mt = 0; mt < 4; mt++)
#pragma unroll
        for (int nt = 0; nt < 8; nt++)
#pragma unroll
            for (int j = 0; j < 4; j++) acc[mt][nt][j] = 0.0f;

    for (int i = 0; i < nk; i++) {
        cp_wait<NSTAGE - 1>();
        __syncthreads();
        const uint32_t s = sb + (i % NSTAGE) * STAGE;

#pragma unroll
        for (int ks = 0; ks < 2; ks++) {    // two k16 steps per BK=32
            uint32_t ah[4][4], al[4][4], bh[4][4], bl[4][4];
#pragma unroll
            for (int mt = 0; mt < 4; mt++) {
                const uint32_t ad = s + A_H + (wm + mt * 16 + lr) * ROWB + ks * 32 + lk;
                ldsm4(ah[mt], ad);
                ldsm4(al[mt], ad + (A_L - A_H));
            }
#pragma unroll
            for (int p = 0; p < 4; p++) {
                const uint32_t bd = s + B_H + (wn + p * 16 + lr) * ROWB + ks * 32 + lk;
                ldsm4(bh[p], bd);
                ldsm4(bl[p], bd + (B_L - B_H));
            }
            // pass 0: Ah*Bh
#pragma unroll
            for (int mt = 0; mt < 4; mt++)
#pragma unroll
                for (int nt = 0; nt < 8; nt++)
                    mma_bf16(acc[mt][nt], ah[mt],
                             bh[nt >> 1][nt & 1], bh[nt >> 1][2 + (nt & 1)]);
            // pass 1: Ah*Bl
#pragma unroll
            for (int mt = 0; mt < 4; mt++)
#pragma unroll
                for (int nt = 0; nt < 8; nt++)
                    mma_bf16(acc[mt][nt], ah[mt],
                             bl[nt >> 1][nt & 1], bl[nt >> 1][2 + (nt & 1)]);
            // pass 2: Al*Bh
#pragma unroll
            for (int mt = 0; mt < 4; mt++)
#pragma unroll
                for (int nt = 0; nt < 8; nt++)
                    mma_bf16(acc[mt][nt], al[mt],
                             bh[nt >> 1][nt & 1], bh[nt >> 1][2 + (nt & 1)]);
        }

        __syncthreads();
        if (i + NSTAGE < nk) load_stage(i % NSTAGE, (i + NSTAGE) * BK);
        cp_commit();
    }

    // ---- epilogue: each warp owns a 64x64 tile ----
    const int er = lane >> 2;
    const int ec = (lane & 3) * 2;
#pragma unroll
    for (int mt = 0; mt < 4; mt++) {
#pragma unroll
        for (int nt = 0; nt < 8; nt++) {
            const int row = bm + wm + mt * 16 + er;
            const int col = bn + wn + nt * 8 + ec;
            const ll o0 = (ll)bz * sC + (ll)row * N + col;
            const ll o8 = o0 + 8LL * N;
            float c0 = acc[mt][nt][0], c1 = acc[mt][nt][1];
            float c2 = acc[mt][nt][2], c3 = acc[mt][nt][3];
            if (EPI == 2) {
                bf16 h0 = __float2bfloat16(c0), h1 = __float2bfloat16(c1);
                bf16 h2 = __float2bfloat16(c2), h3 = __float2bfloat16(c3);
                *(__nv_bfloat162*)(Ch + o0) = __halves2bfloat162(h0, h1);
                *(__nv_bfloat162*)(Ch + o8) = __halves2bfloat162(h2, h3);
                *(__nv_bfloat162*)(Cl + o0) = __halves2bfloat162(
                    __float2bfloat16(c0 - __bfloat162float(h0)),
                    __float2bfloat16(c1 - __bfloat162float(h1)));
                *(__nv_bfloat162*)(Cl + o8) = __halves2bfloat162(
                    __float2bfloat16(c2 - __bfloat162float(h2)),
                    __float2bfloat16(c3 - __bfloat162float(h3)));
            } else {
                if (EPI == 1) {
                    const float b0 = bias[col], b1 = bias[col + 1];
                    c0 += b0; c1 += b1; c2 += b0; c3 += b1;
                }
                *(float2*)(Cf + o0) = make_float2(c0, c1);
                *(float2*)(Cf + o8) = make_float2(c2, c3);
            }
        }
    }
}

// ---------------------------------------------------------------------------
// fp32 -> (hi, lo) bf16 split, elementwise
// ---------------------------------------------------------------------------
__global__ __launch_bounds__(256)
void split_kernel(const float* __restrict__ in, bf16* __restrict__ h,
                  bf16* __restrict__ l, ll n4)
{
    ll i = (ll)blockIdx.x * 256 + threadIdx.x;
    if (i >= n4) return;
    float4 v = *(const float4*)(in + i * 4);
    float f[4] = {v.x, v.y, v.z, v.w};
    bf16 hh[4], lo[4];
#pragma unroll
    for (int j = 0; j < 4; j++) {
        hh[j] = __float2bfloat16(f[j]);
        lo[j] = __float2bfloat16(f[j] - __bfloat162float(hh[j]));
    }
    *(__nv_bfloat162*)(h + i * 4)     = __halves2bfloat162(hh[0], hh[1]);
    *(__nv_bfloat162*)(h + i * 4 + 2) = __halves2bfloat162(hh[2], hh[3]);
    *(__nv_bfloat162*)(l + i * 4)     = __halves2bfloat162(lo[0], lo[1]);
    *(__nv_bfloat162*)(l + i * 4 + 2) = __halves2bfloat162(lo[2], lo[3]);
}

// ---------------------------------------------------------------------------
// Transpose + split: W[R,C] fp32 -> T[C,R] (hi, lo) bf16
// ---------------------------------------------------------------------------
__global__ __launch_bounds__(256)
void tsplit_kernel(const float* __restrict__ W, bf16* __restrict__ Th,
                   bf16* __restrict__ Tl, int R, int C)
{
    __shared__ float t[32][33];
    const int bx = blockIdx.x * 32;   // C index
    const int by = blockIdx.y * 32;   // R index
    const int x = threadIdx.x, y = threadIdx.y;   // (32, 8)
#pragma unroll
    for (int j = 0; j < 32; j += 8)
        t[y + j][x] = W[(ll)(by + y + j) * C + bx + x];
    __syncthreads();
#pragma unroll
    for (int j = 0; j < 32; j += 8) {
        float f = t[x][y + j];
        bf16 h = __float2bfloat16(f);
        bf16 l = __float2bfloat16(f - __bfloat162float(h));
        Th[(ll)(bx + y + j) * R + by + x] = h;
        Tl[(ll)(bx + y + j) * R + by + x] = l;
    }
}

// ---------------------------------------------------------------------------
// Row softmax over N=2048, emits split bf16 probabilities
// ---------------------------------------------------------------------------
__global__ __launch_bounds__(256)
void softmax_split_kernel(const float* __restrict__ S, bf16* __restrict__ Ph,
                          bf16* __restrict__ Pl)
{
    const int N = 2048;
    const ll row = blockIdx.x;
    const float* p = S + row * N;
    const int t = threadIdx.x;

    float v[8];
#pragma unroll
    for (int u = 0; u < 8; u++) v[u] = p[t + u * 256];

    float mx = v[0];
#pragma unroll
    for (int u = 1; u < 8; u++) mx = fmaxf(mx, v[u]);

    __shared__ float red[256];
    red[t] = mx;
    __syncthreads();
    for (int s = 128; s > 0; s >>= 1) {
        if (t < s) red[t] = fmaxf(red[t], red[t + s]);
        __syncthreads();
    }
    mx = red[0];
    __syncthreads();

    float sum = 0.0f;
#pragma unroll
    for (int u = 0; u < 8; u++) {
        v[u] = __expf(v[u] - mx);
        sum += v[u];
    }
    red[t] = sum;
    __syncthreads();
    for (int s = 128; s > 0; s >>= 1) {
        if (t < s) red[t] += red[t + s];
        __syncthreads();
    }
    const float inv = __frcp_rn(red[0]);

#pragma unroll
    for (int u = 0; u < 8; u++) {
        float pr = v[u] * inv;
        bf16 h = __float2bfloat16(pr);
        bf16 l = __float2bfloat16(pr - __bfloat162float(h));
        Ph[row * N + t + u * 256] = h;
        Pl[row * N + t + u * 256] = l;
    }
}

// ---------------------------------------------------------------------------
// kernel_launch — graph-capturable, allocation-free
// Inputs: S1, S2, Wq, Wk, Wv, Wo, bo. Output: fp32 [8,2048,512].
// ---------------------------------------------------------------------------
extern "C" void kernel_launch(void* const* d_in, const int* in_sizes, int n_in,
                              void* d_out, int out_size)
{
    const float* S1 = (const float*)d_in[0];
    const float* S2 = (const float*)d_in[1];
    const float* Wq = (const float*)d_in[2];
    const float* Wk = (const float*)d_in[3];
    const float* Wv = (const float*)d_in[4];
    const float* Wo = (const float*)d_in[5];
    const float* bo = (const float*)d_in[6];
    float* out = (float*)d_out;

    bf16 *s1h, *s1l, *s2h, *s2l, *wqth, *wqtl, *wkth, *wktl, *wvth, *wvtl,
         *woth, *wotl, *qh, *ql, *kh, *kl, *vth, *vtl, *ph, *pl, *oh, *ol;
    float* sc;
    cudaGetSymbolAddress((void**)&s1h, g_s1h);  cudaGetSymbolAddress((void**)&s1l, g_s1l);
    cudaGetSymbolAddress((void**)&s2h, g_s2h);  cudaGetSymbolAddress((void**)&s2l, g_s2l);
    cudaGetSymbolAddress((void**)&wqth, g_wqth); cudaGetSymbolAddress((void**)&wqtl, g_wqtl);
    cudaGetSymbolAddress((void**)&wkth, g_wkth); cudaGetSymbolAddress((void**)&wktl, g_wktl);
    cudaGetSymbolAddress((void**)&wvth, g_wvth); cudaGetSymbolAddress((void**)&wvtl, g_wvtl);
    cudaGetSymbolAddress((void**)&woth, g_woth); cudaGetSymbolAddress((void**)&wotl, g_wotl);
    cudaGetSymbolAddress((void**)&qh, g_qh);    cudaGetSymbolAddress((void**)&ql, g_ql);
    cudaGetSymbolAddress((void**)&kh, g_kh);    cudaGetSymbolAddress((void**)&kl, g_kl);
    cudaGetSymbolAddress((void**)&vth, g_vth);  cudaGetSymbolAddress((void**)&vtl, g_vtl);
    cudaGetSymbolAddress((void**)&sc, g_sc);
    cudaGetSymbolAddress((void**)&ph, g_ph);    cudaGetSymbolAddress((void**)&pl, g_pl);
    cudaGetSymbolAddress((void**)&oh, g_oh);    cudaGetSymbolAddress((void**)&ol, g_ol);

    cudaFuncSetAttribute(mma_gemm<0>, cudaFuncAttributeMaxDynamicSharedMemorySize, SMEM_SZ);
    cudaFuncSetAttribute(mma_gemm<1>, cudaFuncAttributeMaxDynamicSharedMemorySize, SMEM_SZ);
    cudaFuncSetAttribute(mma_gemm<2>, cudaFuncAttributeMaxDynamicSharedMemorySize, SMEM_SZ);

    const int MQ = B_ * N2_;   // 16384

    // ---- pre-pass: split activations, transpose+split weights ----
    split_kernel<<<(unsigned)(S_ELEMS / 4 / 256), 256>>>(S1, s1h, s1l, S_ELEMS / 4);
    split_kernel<<<(unsigned)(S_ELEMS / 4 / 256), 256>>>(S2, s2h, s2l, S_ELEMS / 4);
    tsplit_kernel<<<dim3(ID / 32, QD / 32), dim3(32, 8)>>>(Wq, wqth, wqtl, QD, ID);
    tsplit_kernel<<<dim3(ID / 32, QD / 32), dim3(32, 8)>>>(Wk, wkth, wktl, QD, ID);
    tsplit_kernel<<<dim3(ID / 32, QD / 32), dim3(32, 8)>>>(Wv, wvth, wvtl, QD, ID);
    tsplit_kernel<<<dim3(QD / 32, ID / 32), dim3(32, 8)>>>(Wo, woth, wotl, ID, QD);

    // ---- G1: Q = S2 · WqT^T  [16384,1024], K=512 ----
    mma_gemm<2><<<dim3(ID / BN, MQ / BM, 1), 256, SMEM_SZ>>>(
        s2h, s2l, wqth, wqtl, nullptr, qh, ql, nullptr, MQ, ID, QD, 0, 0, 0);
    // ---- G2: K = S1 · WkT^T ----
    mma_gemm<2><<<dim3(ID / BN, MQ / BM, 1), 256, SMEM_SZ>>>(
        s1h, s1l, wkth, wktl, nullptr, kh, kl, nullptr, MQ, ID, QD, 0, 0, 0);
    // ---- G3: VT[b] = WvT · S1[b]^T  [1024,2048], K=512, batched ----
    mma_gemm<2><<<dim3(N1_ / BN, ID / BM, B_), 256, SMEM_SZ>>>(
        wvth, wvtl, s1h, s1l, nullptr, vth, vtl, nullptr,
        ID, N1_, QD, 0, (ll)N1_ * QD, (ll)ID * N1_);
    // ---- G4: S[b] = Q[b] · K[b]^T  [2048,2048], K=1024 ----
    mma_gemm<0><<<dim3(N1_ / BN, N2_ / BM, B_), 256, SMEM_SZ>>>(
        qh, ql, kh, kl, sc, nullptr, nullptr, nullptr,
        N2_, N1_, ID, (ll)N2_ * ID, (ll)N1_ * ID, (ll)N2_ * N1_);
    // ---- softmax -> split P ----
    softmax_split_kernel<<<B_ * N2_, 256>>>(sc, ph, pl);
    // ---- G6: O[b] = P[b] · VT[b]^T  [2048,1024], K=2048 ----
    mma_gemm<2><<<dim3(ID / BN, N2_ / BM, B_), 256, SMEM_SZ>>>(
        ph, pl, vth, vtl, nullptr, oh, ol, nullptr,
        N2_, ID, N1_, (ll)N2_ * N1_, (ll)ID * N1_, (ll)N2_ * ID);
    // ---- G7: out = O · WoT^T + bo  [16384,512], K=1024 ----
    mma_gemm<1><<<dim3(QD / BN, MQ / BM, 1), 256, SMEM_SZ>>>(
        oh, ol, woth, wotl, out, nullptr, nullptr, bo, MQ, QD, ID, 0, 0, 0);
}

// round 7
// speedup vs baseline: 3.1184x; 1.4410x over previous
#include <cuda_runtime.h>
#include <cuda_bf16.h>
#include <cuda_fp16.h>
#include <cstdint>

using bf16 = __nv_bfloat16;
using ll = long long;

// ============================================================================
// CrossAttention, mma.sync (HMMA). Two precision chains:
//  LOGIT chain (exp-amplified): 3-pass split-bf16  (fp32-class)
//    G1: Q = S2·WqT^T   G2: K = S1·WkT^T   G4: S = Q·K^T
//  VALUE chain (linear error): 1-pass fp16
//    G3: VT = WvT·S1^T  G6: O = P·VT^T     G7: out = O·WoT^T + bo
// All GEMMs NT: C[m,n] = sum_k A[m,k]*B[n,k].
// We sit at the legacy mma.sync issue ceiling (~0.28 HMMA/cyc/SM), so the
// only lever is fewer MMAs: 618 -> 412 GF-equivalent.
// ============================================================================

static constexpr int B_  = 8;
static constexpr int N1_ = 2048;
static constexpr int N2_ = 2048;
static constexpr int QD  = 512;
static constexpr int ID  = 1024;

static constexpr ll S_ELEMS  = (ll)B_ * N2_ * QD;
static constexpr ll QK_ELEMS = (ll)B_ * N2_ * ID;
static constexpr ll SC_ELEMS = (ll)B_ * N2_ * N1_;

// logit chain (bf16 split)
__device__ bf16 g_s1h[S_ELEMS], g_s1l[S_ELEMS];
__device__ bf16 g_s2h[S_ELEMS], g_s2l[S_ELEMS];
__device__ bf16 g_wqth[ID * QD], g_wqtl[ID * QD];
__device__ bf16 g_wkth[ID * QD], g_wktl[ID * QD];
__device__ bf16 g_qh[QK_ELEMS], g_ql[QK_ELEMS];
__device__ bf16 g_kh[QK_ELEMS], g_kl[QK_ELEMS];
__device__ float g_sc[SC_ELEMS];
// value chain (fp16 single)
__device__ __half g_s1f[S_ELEMS];
__device__ __half g_wvtf[ID * QD];
__device__ __half g_wotf[QD * ID];
__device__ __half g_vtf[QK_ELEMS];
__device__ __half g_pf[SC_ELEMS];
__device__ __half g_of[QK_ELEMS];

// ---------------------------------------------------------------------------
// PTX helpers (baseline sm_80-class instructions only)
// ---------------------------------------------------------------------------
__device__ __forceinline__ uint32_t smem_u32(const void* p) {
    uint32_t a;
    asm("{ .reg .u64 t; cvta.to.shared.u64 t, %1; cvt.u32.u64 %0, t; }"
        : "=r"(a) : "l"(p));
    return a;
}
__device__ __forceinline__ void cp16(uint32_t s, const void* g) {
    asm volatile("cp.async.cg.shared.global [%0], [%1], 16;"
                 :: "r"(s), "l"(g) : "memory");
}
__device__ __forceinline__ void cp_commit() {
    asm volatile("cp.async.commit_group;" ::: "memory");
}
template <int N>
__device__ __forceinline__ void cp_wait() {
    asm volatile("cp.async.wait_group %0;" :: "n"(N) : "memory");
}
__device__ __forceinline__ void ldsm4(uint32_t* r, uint32_t addr) {
    asm volatile("ldmatrix.sync.aligned.m8n8.x4.shared.b16 {%0,%1,%2,%3}, [%4];"
                 : "=r"(r[0]), "=r"(r[1]), "=r"(r[2]), "=r"(r[3]) : "r"(addr));
}
__device__ __forceinline__ void mma_bf16(float* c, const uint32_t* a,
                                         uint32_t b0, uint32_t b1) {
    asm volatile(
        "mma.sync.aligned.m16n8k16.row.col.f32.bf16.bf16.f32 "
        "{%0,%1,%2,%3}, {%4,%5,%6,%7}, {%8,%9}, {%0,%1,%2,%3};"
        : "+f"(c[0]), "+f"(c[1]), "+f"(c[2]), "+f"(c[3])
        : "r"(a[0]), "r"(a[1]), "r"(a[2]), "r"(a[3]), "r"(b0), "r"(b1));
}
__device__ __forceinline__ void mma_f16(float* c, const uint32_t* a,
                                        uint32_t b0, uint32_t b1) {
    asm volatile(
        "mma.sync.aligned.m16n8k16.row.col.f32.f16.f16.f32 "
        "{%0,%1,%2,%3}, {%4,%5,%6,%7}, {%8,%9}, {%0,%1,%2,%3};"
        : "+f"(c[0]), "+f"(c[1]), "+f"(c[2]), "+f"(c[3])
        : "r"(a[0]), "r"(a[1]), "r"(a[2]), "r"(a[3]), "r"(b0), "r"(b1));
}

// ---------------------------------------------------------------------------
// GEMM: BM=128, BN=256, BK=32, 256 thr, warp grid 2(M)x4(N) -> 64x64/warp.
// MODE 0: 3-pass split-bf16 (Ah/Al/Bh/Bl).  MODE 1: 1-pass fp16 (Ah/Bh only).
// EPI: 0 fp32, 1 fp32+bias, 2 split-bf16 (Ch,Cl), 3 fp16 (Ch).
// smem rows padded to 80 B -> ldmatrix conflict-free. 3-stage cp.async.
// ---------------------------------------------------------------------------
static constexpr int BM = 128, BN = 256, BK = 32;
static constexpr int ROWB = 80;
static constexpr int NSTAGE = 3;
static constexpr int STAGE3 = 61440;           // A_H,A_L,B_H,B_L
static constexpr int STAGE1 = 30720;           // A, B
static constexpr int SMEM3 = NSTAGE * STAGE3;  // 184320
static constexpr int SMEM1 = NSTAGE * STAGE1;  //  92160

template <int EPI, int MODE>
__global__ __launch_bounds__(256, 1)
void mma_gemm(const uint16_t* __restrict__ Ah, const uint16_t* __restrict__ Al,
              const uint16_t* __restrict__ Bh, const uint16_t* __restrict__ Bl,
              float* __restrict__ Cf, uint16_t* __restrict__ Ch,
              uint16_t* __restrict__ Cl, const float* __restrict__ bias,
              int M, int N, int K, ll sA, ll sB, ll sC)
{
    constexpr int AL_OFF = 10240;                       // 128*80
    constexpr int B_OFF  = (MODE == 0) ? 20480 : 10240;
    constexpr int BL_OFF = 20480;                       // 256*80, rel to B_OFF
    constexpr int STG    = (MODE == 0) ? STAGE3 : STAGE1;

    extern __shared__ char smem[];
    const uint32_t sb = smem_u32(smem);
    const int tid = threadIdx.x;
    const int bz  = blockIdx.z;
    const int bm  = blockIdx.y * BM;
    const int bn  = blockIdx.x * BN;

    const uint16_t* pAh = Ah + (ll)bz * sA;
    const uint16_t* pAl = (MODE == 0) ? Al + (ll)bz * sA : nullptr;
    const uint16_t* pBh = Bh + (ll)bz * sB;
    const uint16_t* pBl = (MODE == 0) ? Bl + (ll)bz * sB : nullptr;

    auto load_stage = [&](int buf, int k0) {
        const uint32_t s = sb + buf * STG;
#pragma unroll
        for (int it = 0; it < 2; it++) {
            const int g = tid + it * 256;          // 0..511 (A: 128 rows x 4)
            const int r = g >> 2, c = g & 3;
            const uint32_t so = r * ROWB + c * 16;
            const ll ga = (ll)(bm + r) * K + k0 + c * 8;
            cp16(s + so, pAh + ga);
            if (MODE == 0) cp16(s + AL_OFF + so, pAl + ga);
        }
#pragma unroll
        for (int it = 0; it < 4; it++) {
            const int g = tid + it * 256;          // 0..1023 (B: 256 rows x 4)
            const int r = g >> 2, c = g & 3;
            const uint32_t so = r * ROWB + c * 16;
            const ll gb = (ll)(bn + r) * K + k0 + c * 8;
            cp16(s + B_OFF + so, pBh + gb);
            if (MODE == 0) cp16(s + B_OFF + BL_OFF + so, pBl + gb);
        }
    };

    const int nk = K / BK;
    load_stage(0, 0);      cp_commit();
    load_stage(1, BK);     cp_commit();
    load_stage(2, 2 * BK); cp_commit();

    const int lane = tid & 31, wid = tid >> 5;
    const int wm = (wid & 1) * 64;
    const int wn = (wid >> 1) * 64;
    const int lr = lane & 15;
    const int lk = (lane >> 4) * 16;

    float acc[4][8][4];
#pragma unroll
    for (int mt = 0; mt < 4; mt++)
#pragma unroll
        for (int nt = 0; nt < 8; nt++)
#pragma unroll
            for (int j = 0; j < 4; j++) acc[mt][nt][j] = 0.0f;

    for (int i = 0; i < nk; i++) {
        cp_wait<NSTAGE - 1>();
        __syncthreads();
        const uint32_t s = sb + (i % NSTAGE) * STG;

#pragma unroll
        for (int ks = 0; ks < 2; ks++) {
            uint32_t ah[4][4], bh[4][4];
            uint32_t al[MODE == 0 ? 4 : 1][4], bl[MODE == 0 ? 4 : 1][4];
#pragma unroll
            for (int mt = 0; mt < 4; mt++) {
                const uint32_t ad = s + (wm + mt * 16 + lr) * ROWB + ks * 32 + lk;
                ldsm4(ah[mt], ad);
                if (MODE == 0) ldsm4(al[mt], ad + AL_OFF);
            }
#pragma unroll
            for (int p = 0; p < 4; p++) {
                const uint32_t bd = s + B_OFF + (wn + p * 16 + lr) * ROWB + ks * 32 + lk;
                ldsm4(bh[p], bd);
                if (MODE == 0) ldsm4(bl[p], bd + BL_OFF);
            }
            if (MODE == 1) {
#pragma unroll
                for (int mt = 0; mt < 4; mt++)
#pragma unroll
                    for (int nt = 0; nt < 8; nt++)
                        mma_f16(acc[mt][nt], ah[mt],
                                bh[nt >> 1][nt & 1], bh[nt >> 1][2 + (nt & 1)]);
            } else {
#pragma unroll
                for (int mt = 0; mt < 4; mt++)
#pragma unroll
                    for (int nt = 0; nt < 8; nt++)
                        mma_bf16(acc[mt][nt], ah[mt],
                                 bh[nt >> 1][nt & 1], bh[nt >> 1][2 + (nt & 1)]);
#pragma unroll
                for (int mt = 0; mt < 4; mt++)
#pragma unroll
                    for (int nt = 0; nt < 8; nt++)
                        mma_bf16(acc[mt][nt], ah[mt],
                                 bl[nt >> 1][nt & 1], bl[nt >> 1][2 + (nt & 1)]);
#pragma unroll
                for (int mt = 0; mt < 4; mt++)
#pragma unroll
                    for (int nt = 0; nt < 8; nt++)
                        mma_bf16(acc[mt][nt], al[mt],
                                 bh[nt >> 1][nt & 1], bh[nt >> 1][2 + (nt & 1)]);
            }
        }

        __syncthreads();
        if (i + NSTAGE < nk) load_stage(i % NSTAGE, (i + NSTAGE) * BK);
        cp_commit();
    }

    // ---- epilogue: each warp owns a 64x64 tile ----
    const int er = lane >> 2;
    const int ec = (lane & 3) * 2;
#pragma unroll
    for (int mt = 0; mt < 4; mt++) {
#pragma unroll
        for (int nt = 0; nt < 8; nt++) {
            const int row = bm + wm + mt * 16 + er;
            const int col = bn + wn + nt * 8 + ec;
            const ll o0 = (ll)bz * sC + (ll)row * N + col;
            const ll o8 = o0 + 8LL * N;
            float c0 = acc[mt][nt][0], c1 = acc[mt][nt][1];
            float c2 = acc[mt][nt][2], c3 = acc[mt][nt][3];
            if (EPI == 2) {
                bf16 h0 = __float2bfloat16(c0), h1 = __float2bfloat16(c1);
                bf16 h2 = __float2bfloat16(c2), h3 = __float2bfloat16(c3);
                *(__nv_bfloat162*)(Ch + o0) = __halves2bfloat162(h0, h1);
                *(__nv_bfloat162*)(Ch + o8) = __halves2bfloat162(h2, h3);
                *(__nv_bfloat162*)(Cl + o0) = __halves2bfloat162(
                    __float2bfloat16(c0 - __bfloat162float(h0)),
                    __float2bfloat16(c1 - __bfloat162float(h1)));
                *(__nv_bfloat162*)(Cl + o8) = __halves2bfloat162(
                    __float2bfloat16(c2 - __bfloat162float(h2)),
                    __float2bfloat16(c3 - __bfloat162float(h3)));
            } else if (EPI == 3) {
                *(__half2*)(Ch + o0) = __floats2half2_rn(c0, c1);
                *(__half2*)(Ch + o8) = __floats2half2_rn(c2, c3);
            } else {
                if (EPI == 1) {
                    const float b0 = bias[col], b1 = bias[col + 1];
                    c0 += b0; c1 += b1; c2 += b0; c3 += b1;
                }
                *(float2*)(Cf + o0) = make_float2(c0, c1);
                *(float2*)(Cf + o8) = make_float2(c2, c3);
            }
        }
    }
}

// ---------------------------------------------------------------------------
// fp32 -> (hi, lo) bf16 split, elementwise
// ---------------------------------------------------------------------------
__global__ __launch_bounds__(256)
void split_kernel(const float* __restrict__ in, bf16* __restrict__ h,
                  bf16* __restrict__ l, ll n4)
{
    ll i = (ll)blockIdx.x * 256 + threadIdx.x;
    if (i >= n4) return;
    float4 v = *(const float4*)(in + i * 4);
    float f[4] = {v.x, v.y, v.z, v.w};
    bf16 hh[4], lo[4];
#pragma unroll
    for (int j = 0; j < 4; j++) {
        hh[j] = __float2bfloat16(f[j]);
        lo[j] = __float2bfloat16(f[j] - __bfloat162float(hh[j]));
    }
    *(__nv_bfloat162*)(h + i * 4)     = __halves2bfloat162(hh[0], hh[1]);
    *(__nv_bfloat162*)(h + i * 4 + 2) = __halves2bfloat162(hh[2], hh[3]);
    *(__nv_bfloat162*)(l + i * 4)     = __halves2bfloat162(lo[0], lo[1]);
    *(__nv_bfloat162*)(l + i * 4 + 2) = __halves2bfloat162(lo[2], lo[3]);
}

// ---------------------------------------------------------------------------
// fp32 -> fp16 cast, elementwise
// ---------------------------------------------------------------------------
__global__ __launch_bounds__(256)
void f16cast_kernel(const float* __restrict__ in, __half* __restrict__ out, ll n4)
{
    ll i = (ll)blockIdx.x * 256 + threadIdx.x;
    if (i >= n4) return;
    float4 v = *(const float4*)(in + i * 4);
    *(__half2*)(out + i * 4)     = __floats2half2_rn(v.x, v.y);
    *(__half2*)(out + i * 4 + 2) = __floats2half2_rn(v.z, v.w);
}

// ---------------------------------------------------------------------------
// Transpose + split: W[R,C] fp32 -> T[C,R] (hi, lo) bf16
// ---------------------------------------------------------------------------
__global__ __launch_bounds__(256)
void tsplit_kernel(const float* __restrict__ W, bf16* __restrict__ Th,
                   bf16* __restrict__ Tl, int R, int C)
{
    __shared__ float t[32][33];
    const int bx = blockIdx.x * 32;
    const int by = blockIdx.y * 32;
    const int x = threadIdx.x, y = threadIdx.y;   // (32, 8)
#pragma unroll
    for (int j = 0; j < 32; j += 8)
        t[y + j][x] = W[(ll)(by + y + j) * C + bx + x];
    __syncthreads();
#pragma unroll
    for (int j = 0; j < 32; j += 8) {
        float f = t[x][y + j];
        bf16 h = __float2bfloat16(f);
        bf16 l = __float2bfloat16(f - __bfloat162float(h));
        Th[(ll)(bx + y + j) * R + by + x] = h;
        Tl[(ll)(bx + y + j) * R + by + x] = l;
    }
}

// ---------------------------------------------------------------------------
// Transpose to fp16: W[R,C] fp32 -> T[C,R] fp16
// ---------------------------------------------------------------------------
__global__ __launch_bounds__(256)
void tf16_kernel(const float* __restrict__ W, __half* __restrict__ T, int R, int C)
{
    __shared__ float t[32][33];
    const int bx = blockIdx.x * 32;
    const int by = blockIdx.y * 32;
    const int x = threadIdx.x, y = threadIdx.y;   // (32, 8)
#pragma unroll
    for (int j = 0; j < 32; j += 8)
        t[y + j][x] = W[(ll)(by + y + j) * C + bx + x];
    __syncthreads();
#pragma unroll
    for (int j = 0; j < 32; j += 8)
        T[(ll)(bx + y + j) * R + by + x] = __float2half_rn(t[x][y + j]);
}

// ---------------------------------------------------------------------------
// Row softmax over N=2048, emits fp16 probabilities
// ---------------------------------------------------------------------------
__global__ __launch_bounds__(256)
void softmax_f16_kernel(const float* __restrict__ S, __half* __restrict__ P)
{
    const int N = 2048;
    const ll row = blockIdx.x;
    const float* p = S + row * N;
    const int t = threadIdx.x;

    float v[8];
#pragma unroll
    for (int u = 0; u < 8; u++) v[u] = p[t + u * 256];

    float mx = v[0];
#pragma unroll
    for (int u = 1; u < 8; u++) mx = fmaxf(mx, v[u]);

    __shared__ float red[256];
    red[t] = mx;
    __syncthreads();
    for (int s = 128; s > 0; s >>= 1) {
        if (t < s) red[t] = fmaxf(red[t], red[t + s]);
        __syncthreads();
    }
    mx = red[0];
    __syncthreads();

    float sum = 0.0f;
#pragma unroll
    for (int u = 0; u < 8; u++) {
        v[u] = __expf(v[u] - mx);
        sum += v[u];
    }
    red[t] = sum;
    __syncthreads();
    for (int s = 128; s > 0; s >>= 1) {
        if (t < s) red[t] += red[t + s];
        __syncthreads();
    }
    const float inv = __frcp_rn(red[0]);

#pragma unroll
    for (int u = 0; u < 8; u++)
        P[row * N + t + u * 256] = __float2half_rn(v[u] * inv);
}

// ---------------------------------------------------------------------------
// kernel_launch — graph-capturable, allocation-free
// Inputs: S1, S2, Wq, Wk, Wv, Wo, bo. Output: fp32 [8,2048,512].
// ---------------------------------------------------------------------------
extern "C" void kernel_launch(void* const* d_in, const int* in_sizes, int n_in,
                              void* d_out, int out_size)
{
    const float* S1 = (const float*)d_in[0];
    const float* S2 = (const float*)d_in[1];
    const float* Wq = (const float*)d_in[2];
    const float* Wk = (const float*)d_in[3];
    const float* Wv = (const float*)d_in[4];
    const float* Wo = (const float*)d_in[5];
    const float* bo = (const float*)d_in[6];
    float* out = (float*)d_out;

    bf16 *s1h, *s1l, *s2h, *s2l, *wqth, *wqtl, *wkth, *wktl, *qh, *ql, *kh, *kl;
    __half *s1f, *wvtf, *wotf, *vtf, *pf, *of;
    float* sc;
    cudaGetSymbolAddress((void**)&s1h, g_s1h);  cudaGetSymbolAddress((void**)&s1l, g_s1l);
    cudaGetSymbolAddress((void**)&s2h, g_s2h);  cudaGetSymbolAddress((void**)&s2l, g_s2l);
    cudaGetSymbolAddress((void**)&wqth, g_wqth); cudaGetSymbolAddress((void**)&wqtl, g_wqtl);
    cudaGetSymbolAddress((void**)&wkth, g_wkth); cudaGetSymbolAddress((void**)&wktl, g_wktl);
    cudaGetSymbolAddress((void**)&qh, g_qh);    cudaGetSymbolAddress((void**)&ql, g_ql);
    cudaGetSymbolAddress((void**)&kh, g_kh);    cudaGetSymbolAddress((void**)&kl, g_kl);
    cudaGetSymbolAddress((void**)&sc, g_sc);
    cudaGetSymbolAddress((void**)&s1f, g_s1f);
    cudaGetSymbolAddress((void**)&wvtf, g_wvtf);
    cudaGetSymbolAddress((void**)&wotf, g_wotf);
    cudaGetSymbolAddress((void**)&vtf, g_vtf);
    cudaGetSymbolAddress((void**)&pf, g_pf);
    cudaGetSymbolAddress((void**)&of, g_of);

    cudaFuncSetAttribute(mma_gemm<2, 0>, cudaFuncAttributeMaxDynamicSharedMemorySize, SMEM3);
    cudaFuncSetAttribute(mma_gemm<0, 0>, cudaFuncAttributeMaxDynamicSharedMemorySize, SMEM3);
    cudaFuncSetAttribute(mma_gemm<3, 1>, cudaFuncAttributeMaxDynamicSharedMemorySize, SMEM1);
    cudaFuncSetAttribute(mma_gemm<1, 1>, cudaFuncAttributeMaxDynamicSharedMemorySize, SMEM1);

    const int MQ = B_ * N2_;   // 16384

    // ---- pre-pass ----
    split_kernel<<<(unsigned)(S_ELEMS / 4 / 256), 256>>>(S1, s1h, s1l, S_ELEMS / 4);
    split_kernel<<<(unsigned)(S_ELEMS / 4 / 256), 256>>>(S2, s2h, s2l, S_ELEMS / 4);
    f16cast_kernel<<<(unsigned)(S_ELEMS / 4 / 256), 256>>>(S1, s1f, S_ELEMS / 4);
    tsplit_kernel<<<dim3(ID / 32, QD / 32), dim3(32, 8)>>>(Wq, wqth, wqtl, QD, ID);
    tsplit_kernel<<<dim3(ID / 32, QD / 32), dim3(32, 8)>>>(Wk, wkth, wktl, QD, ID);
    tf16_kernel<<<dim3(ID / 32, QD / 32), dim3(32, 8)>>>(Wv, wvtf, QD, ID);
    tf16_kernel<<<dim3(QD / 32, ID / 32), dim3(32, 8)>>>(Wo, wotf, ID, QD);

    // ---- G1: Q = S2 · WqT^T  [16384,1024], K=512 (3-pass bf16) ----
    mma_gemm<2, 0><<<dim3(ID / BN, MQ / BM, 1), 256, SMEM3>>>(
        (const uint16_t*)s2h, (const uint16_t*)s2l,
        (const uint16_t*)wqth, (const uint16_t*)wqtl,
        nullptr, (uint16_t*)qh, (uint16_t*)ql, nullptr, MQ, ID, QD, 0, 0, 0);
    // ---- G2: K = S1 · WkT^T (3-pass bf16) ----
    mma_gemm<2, 0><<<dim3(ID / BN, MQ / BM, 1), 256, SMEM3>>>(
        (const uint16_t*)s1h, (const uint16_t*)s1l,
        (const uint16_t*)wkth, (const uint16_t*)wktl,
        nullptr, (uint16_t*)kh, (uint16_t*)kl, nullptr, MQ, ID, QD, 0, 0, 0);
    // ---- G3: VT[b] = WvT · S1[b]^T  [1024,2048], K=512 (1-pass fp16) ----
    mma_gemm<3, 1><<<dim3(N1_ / BN, ID / BM, B_), 256, SMEM1>>>(
        (const uint16_t*)wvtf, nullptr, (const uint16_t*)s1f, nullptr,
        nullptr, (uint16_t*)vtf, nullptr, nullptr,
        ID, N1_, QD, 0, (ll)N1_ * QD, (ll)ID * N1_);
    // ---- G4: S[b] = Q[b] · K[b]^T  [2048,2048], K=1024 (3-pass bf16) ----
    mma_gemm<0, 0><<<dim3(N1_ / BN, N2_ / BM, B_), 256, SMEM3>>>(
        (const uint16_t*)qh, (const uint16_t*)ql,
        (const uint16_t*)kh, (const uint16_t*)kl,
        sc, nullptr, nullptr, nullptr,
        N2_, N1_, ID, (ll)N2_ * ID, (ll)N1_ * ID, (ll)N2_ * N1_);
    // ---- softmax -> fp16 P ----
    softmax_f16_kernel<<<B_ * N2_, 256>>>(sc, pf);
    // ---- G6: O[b] = P[b] · VT[b]^T  [2048,1024], K=2048 (1-pass fp16) ----
    mma_gemm<3, 1><<<dim3(ID / BN, N2_ / BM, B_), 256, SMEM1>>>(
        (const uint16_t*)pf, nullptr, (const uint16_t*)vtf, nullptr,
        nullptr, (uint16_t*)of, nullptr, nullptr,
        N2_, ID, N1_, (ll)N2_ * N1_, (ll)ID * N1_, (ll)N2_ * ID);
    // ---- G7: out = O · WoT^T + bo  [16384,512], K=1024 (1-pass fp16) ----
    mma_gemm<1, 1><<<dim3(QD / BN, MQ / BM, 1), 256, SMEM1>>>(
        (const uint16_t*)of, nullptr, (const uint16_t*)wotf, nullptr,
        out, nullptr, nullptr, bo, MQ, QD, ID, 0, 0, 0);
}